// round 6
// baseline (speedup 1.0000x reference)
#include <cuda_runtime.h>
#include <cstdint>

#define C_DIM  256
#define L_DIM  4096
#define LM_DIM 36864
#define B_DIM  4

__device__ float g_M[C_DIM * C_DIM];             // M[c1][c2]
__device__ float g_U[B_DIM * C_DIM * L_DIM];     // U[b][c2][l]
__device__ unsigned int g_flags[256];            // [(b*32+lt)*2 + half]

// ---------------- helpers ----------------
__device__ __forceinline__ uint32_t smem_u32(const void* p) {
    uint32_t a;
    asm("{ .reg .u64 t; cvta.to.shared.u64 t, %1; cvt.u32.u64 %0, t; }" : "=r"(a) : "l"(p));
    return a;
}
__device__ __forceinline__ void cp16(uint32_t dst, const void* src) {
    asm volatile("cp.async.cg.shared.global [%0], [%1], 16;" :: "r"(dst), "l"(src) : "memory");
}
__device__ __forceinline__ void cp_commit() {
    asm volatile("cp.async.commit_group;" ::: "memory");
}
template <int N>
__device__ __forceinline__ void cp_wait() {
    asm volatile("cp.async.wait_group %0;" :: "n"(N) : "memory");
}
__device__ __forceinline__ uint32_t tf32_hi(float v) {
    uint32_t h;
    asm("cvt.rna.tf32.f32 %0, %1;" : "=r"(h) : "f"(v));
    return h;
}
__device__ __forceinline__ uint32_t tf32_lo(float v, uint32_t hi) {
    float l = v - __uint_as_float(hi);
    uint32_t r;
    asm("cvt.rna.tf32.f32 %0, %1;" : "=r"(r) : "f"(l));
    return r;
}
__device__ __forceinline__ void mma8(float* d, const uint32_t* a, const uint32_t* b) {
    asm volatile(
        "mma.sync.aligned.m16n8k8.row.col.f32.tf32.tf32.f32 "
        "{%0,%1,%2,%3}, {%4,%5,%6,%7}, {%8,%9}, {%0,%1,%2,%3};"
        : "+f"(d[0]), "+f"(d[1]), "+f"(d[2]), "+f"(d[3])
        : "r"(a[0]), "r"(a[1]), "r"(a[2]), "r"(a[3]), "r"(b[0]), "r"(b[1]));
}
__device__ __forceinline__ unsigned int ld_acq(const unsigned int* p) {
    unsigned int v;
    asm volatile("ld.acquire.gpu.global.u32 %0, [%1];" : "=r"(v) : "l"(p) : "memory");
    return v;
}
__device__ __forceinline__ void st_rel(unsigned int* p, unsigned int v) {
    asm volatile("st.release.gpu.global.u32 [%0], %1;" :: "l"(p), "r"(v) : "memory");
}

// ---------------- Kernel 1: M[c1][c2], 8-way k-split + atomicAdd ----------------
__global__ __launch_bounds__(256) void k1_M(const float* __restrict__ W1,
                                            const float* __restrict__ W2) {
    __shared__ float A[32][33];
    __shared__ float Bs[32][33];
    const int t = threadIdx.x;
    const int c2_0 = blockIdx.x * 32, c1_0 = blockIdx.y * 32, kk = blockIdx.z * 32;
    {
        int r = t >> 3, c4 = (t & 7) * 4;
        float4 a = *(const float4*)&W1[(c1_0 + r) * 768 + kk + c4];
        A[r][c4] = a.x; A[r][c4 + 1] = a.y; A[r][c4 + 2] = a.z; A[r][c4 + 3] = a.w;
        float4 b = *(const float4*)&W2[(c2_0 + r) * 768 + 256 + kk + c4];
        Bs[r][c4] = b.x; Bs[r][c4 + 1] = b.y; Bs[r][c4 + 2] = b.z; Bs[r][c4 + 3] = b.w;
    }
    __syncthreads();
    const int ty = t >> 4, tx = t & 15;
    float a00 = 0.f, a01 = 0.f, a10 = 0.f, a11 = 0.f;
    #pragma unroll
    for (int k = 0; k < 32; ++k) {
        float x0 = A[ty * 2][k], x1 = A[ty * 2 + 1][k];
        float y0 = Bs[tx * 2][k], y1 = Bs[tx * 2 + 1][k];
        a00 += x0 * y0; a01 += x0 * y1; a10 += x1 * y0; a11 += x1 * y1;
    }
    atomicAdd(&g_M[(c1_0 + ty * 2)     * 256 + c2_0 + tx * 2],     a00);
    atomicAdd(&g_M[(c1_0 + ty * 2)     * 256 + c2_0 + tx * 2 + 1], a01);
    atomicAdd(&g_M[(c1_0 + ty * 2 + 1) * 256 + c2_0 + tx * 2],     a10);
    atomicAdd(&g_M[(c1_0 + ty * 2 + 1) * 256 + c2_0 + tx * 2 + 1], a11);
}

// ---------------- Fused heterogeneous kernel ----------------
// Group (b, lt) -> bids [6g, 6g+6): j=0,1 GEMM halves (c2_0=j*128), j=2..5 score slices.
#define PA 136
#define CH_F (32 * PA)                      // 4352 floats / buffer
#define KFS_SMEM (4 * CH_F * 4)             // 69632 B
#define UPIT 132

__global__ __launch_bounds__(256, 2) void kFS(const float* __restrict__ HSI,
                                              const float* __restrict__ MSI,
                                              float* __restrict__ out) {
    extern __shared__ float sm[];
    __shared__ float sc[288];
    const int t = threadIdx.x, wid = t >> 5, lane = t & 31;
    const int grp = blockIdx.x / 6, j = blockIdx.x % 6;
    const int b = grp >> 5, lt = grp & 31;
    const int l0 = lt * 128;
    float* Ub = g_U + (size_t)b * C_DIM * L_DIM;

    if (j < 2) {
        // ================= GEMM block: 128 l x 128 c2 (r3-proven mainloop) =================
        const int c2_0 = j * 128;
        const float* Hb = HSI + (size_t)b * C_DIM * L_DIM;
        const uint32_t sbase = smem_u32(sm);
        const int g = lane >> 2, t4 = lane & 3;
        const int mw = (wid >> 1) * 32, nw = (wid & 1) * 64;
        const int cprow = t >> 5, cpquad = t & 31;

        float d[2][8][4];
        #pragma unroll
        for (int mt = 0; mt < 2; ++mt)
            #pragma unroll
            for (int nt = 0; nt < 8; ++nt)
                #pragma unroll
                for (int i = 0; i < 4; ++i) d[mt][nt][i] = 0.f;

        {   // chunk 0
            float* A0 = sm; float* B0 = sm + CH_F;
            #pragma unroll
            for (int q = 0; q < 4; ++q) {
                int r = cprow + q * 8;
                cp16(sbase + (uint32_t)((A0 - sm + r * PA + cpquad * 4) * 4),
                     &Hb[(size_t)r * L_DIM + l0 + cpquad * 4]);
                cp16(sbase + (uint32_t)((B0 - sm + r * PA + cpquad * 4) * 4),
                     &g_M[r * 256 + c2_0 + cpquad * 4]);
            }
            cp_commit();
        }

        for (int ch = 0; ch < 8; ++ch) {
            if (ch < 7) {
                int p = (ch + 1) & 1;
                int kk = (ch + 1) * 32;
                float* Ab = sm + p * 2 * CH_F;
                float* Bb = Ab + CH_F;
                #pragma unroll
                for (int q = 0; q < 4; ++q) {
                    int r = cprow + q * 8;
                    cp16(sbase + (uint32_t)((Ab - sm + r * PA + cpquad * 4) * 4),
                         &Hb[(size_t)(kk + r) * L_DIM + l0 + cpquad * 4]);
                    cp16(sbase + (uint32_t)((Bb - sm + r * PA + cpquad * 4) * 4),
                         &g_M[(kk + r) * 256 + c2_0 + cpquad * 4]);
                }
                cp_commit();
                cp_wait<1>();
            } else {
                cp_wait<0>();
            }
            __syncthreads();

            const float* As = sm + (ch & 1) * 2 * CH_F;
            const float* Bs = As + CH_F;

            #pragma unroll
            for (int s = 0; s < 4; ++s) {
                const int r0 = 8 * s + t4, r1 = r0 + 4;
                uint32_t ah[2][4], al[2][4];
                #pragma unroll
                for (int mt = 0; mt < 2; ++mt) {
                    int m0 = mw + 16 * mt + g;
                    float v0 = As[r0 * PA + m0];
                    float v1 = As[r0 * PA + m0 + 8];
                    float v2 = As[r1 * PA + m0];
                    float v3 = As[r1 * PA + m0 + 8];
                    ah[mt][0] = tf32_hi(v0); al[mt][0] = tf32_lo(v0, ah[mt][0]);
                    ah[mt][1] = tf32_hi(v1); al[mt][1] = tf32_lo(v1, ah[mt][1]);
                    ah[mt][2] = tf32_hi(v2); al[mt][2] = tf32_lo(v2, ah[mt][2]);
                    ah[mt][3] = tf32_hi(v3); al[mt][3] = tf32_lo(v3, ah[mt][3]);
                }
                #pragma unroll
                for (int ng = 0; ng < 2; ++ng) {
                    uint32_t bh[4][2], bl[4][2];
                    #pragma unroll
                    for (int q = 0; q < 4; ++q) {
                        int n0 = nw + 8 * (ng * 4 + q) + g;
                        float v0 = Bs[r0 * PA + n0];
                        float v1 = Bs[r1 * PA + n0];
                        bh[q][0] = tf32_hi(v0); bl[q][0] = tf32_lo(v0, bh[q][0]);
                        bh[q][1] = tf32_hi(v1); bl[q][1] = tf32_lo(v1, bh[q][1]);
                    }
                    #pragma unroll
                    for (int mt = 0; mt < 2; ++mt)
                        #pragma unroll
                        for (int q = 0; q < 4; ++q)
                            mma8(d[mt][ng * 4 + q], ah[mt], bh[q]);
                    #pragma unroll
                    for (int mt = 0; mt < 2; ++mt)
                        #pragma unroll
                        for (int q = 0; q < 4; ++q)
                            mma8(d[mt][ng * 4 + q], ah[mt], bl[q]);
                    #pragma unroll
                    for (int mt = 0; mt < 2; ++mt)
                        #pragma unroll
                        for (int q = 0; q < 4; ++q)
                            mma8(d[mt][ng * 4 + q], al[mt], bh[q]);
                }
            }
            __syncthreads();
        }

        // staged epilogue: Usm[c2_local(128)][l_local(128)] pitch 132, then coalesced STG
        float* Usm = sm;
        #pragma unroll
        for (int mt = 0; mt < 2; ++mt) {
            int row0 = mw + 16 * mt + (lane >> 2);
            #pragma unroll
            for (int nt = 0; nt < 8; ++nt) {
                int col0 = nw + 8 * nt + 2 * (lane & 3);
                Usm[col0 * UPIT + row0]           = d[mt][nt][0];
                Usm[(col0 + 1) * UPIT + row0]     = d[mt][nt][1];
                Usm[col0 * UPIT + row0 + 8]       = d[mt][nt][2];
                Usm[(col0 + 1) * UPIT + row0 + 8] = d[mt][nt][3];
            }
        }
        __syncthreads();
        for (int i = t; i < 128 * 32; i += 256) {
            int c2 = i >> 5, q = (i & 31) * 4;
            float4 v = *(const float4*)&Usm[c2 * UPIT + q];
            *(float4*)&Ub[(size_t)(c2_0 + c2) * L_DIM + l0 + q] = v;
        }
        __syncthreads();
        if (t == 0) {
            asm volatile("fence.acq_rel.gpu;" ::: "memory");
            st_rel(&g_flags[grp * 2 + j], 1u);
        }
    } else {
        // ================= score block: 32 l, 288 m (r1-proven inner loop) =================
        const int sl0 = l0 + (j - 2) * 32;
        float (*us)[33] = (float (*)[33])sm;     // 256 x 33

        if (t == 0) {
            const unsigned int* f = &g_flags[grp * 2];
            while (ld_acq(&f[0]) == 0u) __nanosleep(128);
            while (ld_acq(&f[1]) == 0u) __nanosleep(128);
        }
        __syncthreads();

        for (int i = t; i < 256 * 32; i += 256) {
            int c2 = i >> 5, l = i & 31;
            us[c2][l] = Ub[(size_t)c2 * L_DIM + sl0 + l];
        }
        __syncthreads();

        const float* mp = MSI + (size_t)b * C_DIM * LM_DIM + (size_t)sl0 * 9;
        for (int i = t; i < 288; i += 256) {
            const int ll = i / 9;
            const float* col = mp + i;
            float acc = 0.f;
            #pragma unroll 8
            for (int c2 = 0; c2 < 256; ++c2)
                acc += us[c2][ll] * col[(size_t)c2 * LM_DIM];
            sc[i] = acc;
        }
        __syncthreads();

        if (t < 32) {
            float best = sc[t * 9];
            int bn = 0;
            #pragma unroll
            for (int jj = 1; jj < 9; ++jj) {
                float v = sc[t * 9 + jj];
                if (v > best) { best = v; bn = jj; }   // strict > = first max (jnp.argmax)
            }
            float2 o = make_float2((float)(bn / 3) - 1.f, (float)(bn % 3) - 1.f);
            *(float2*)&out[(size_t)(b * L_DIM + sl0 + t) * 2] = o;
        }
    }
}

// ---------------- launch ----------------
extern "C" void kernel_launch(void* const* d_in, const int* in_sizes, int n_in,
                              void* d_out, int out_size) {
    const float* HSI = (const float*)d_in[2];
    const float* MSI = (const float*)d_in[3];
    const float* W1  = (const float*)d_in[4];
    const float* W2  = (const float*)d_in[5];
    float* out = (float*)d_out;

    void* mp = nullptr; void* fp = nullptr;
    cudaGetSymbolAddress(&mp, g_M);
    cudaGetSymbolAddress(&fp, g_flags);
    cudaMemsetAsync(mp, 0, C_DIM * C_DIM * sizeof(float), 0);
    cudaMemsetAsync(fp, 0, 256 * sizeof(unsigned int), 0);

    k1_M<<<dim3(8, 8, 8), 256>>>(W1, W2);

    cudaFuncSetAttribute(kFS, cudaFuncAttributeMaxDynamicSharedMemorySize, KFS_SMEM);
    kFS<<<768, 256, KFS_SMEM>>>(HSI, MSI, out);
}

// round 8
// speedup vs baseline: 1.8096x; 1.8096x over previous
#include <cuda_runtime.h>
#include <cstdint>

#define C_DIM  256
#define L_DIM  4096
#define LM_DIM 36864
#define B_DIM  4

__device__ float g_M[C_DIM * C_DIM];               // M[c1][c2] (fp32 accum)
__device__ float g_Mhl[C_DIM * C_DIM * 2];         // interleaved {hi,lo} tf32 pairs
__device__ float g_U[B_DIM * C_DIM * L_DIM];       // U[b][c2][l]

// ---------------- helpers ----------------
__device__ __forceinline__ uint32_t smem_u32(const void* p) {
    uint32_t a;
    asm("{ .reg .u64 t; cvta.to.shared.u64 t, %1; cvt.u32.u64 %0, t; }" : "=r"(a) : "l"(p));
    return a;
}
__device__ __forceinline__ void cp16(uint32_t dst, const void* src) {
    asm volatile("cp.async.cg.shared.global [%0], [%1], 16;" :: "r"(dst), "l"(src) : "memory");
}
__device__ __forceinline__ void cp_commit() {
    asm volatile("cp.async.commit_group;" ::: "memory");
}
template <int N>
__device__ __forceinline__ void cp_wait() {
    asm volatile("cp.async.wait_group %0;" :: "n"(N) : "memory");
}
__device__ __forceinline__ uint32_t tf32_hi(float v) {
    uint32_t h;
    asm("cvt.rna.tf32.f32 %0, %1;" : "=r"(h) : "f"(v));
    return h;
}
__device__ __forceinline__ uint32_t tf32_lo(float v, uint32_t hi) {
    float l = v - __uint_as_float(hi);
    uint32_t r;
    asm("cvt.rna.tf32.f32 %0, %1;" : "=r"(r) : "f"(l));
    return r;
}
__device__ __forceinline__ void mma8(float* d, const uint32_t* a, const uint32_t* b) {
    asm volatile(
        "mma.sync.aligned.m16n8k8.row.col.f32.tf32.tf32.f32 "
        "{%0,%1,%2,%3}, {%4,%5,%6,%7}, {%8,%9}, {%0,%1,%2,%3};"
        : "+f"(d[0]), "+f"(d[1]), "+f"(d[2]), "+f"(d[3])
        : "r"(a[0]), "r"(a[1]), "r"(a[2]), "r"(a[3]), "r"(b[0]), "r"(b[1]));
}

// ---------------- Kernel 1: M[c1][c2], 8-way k-split + atomicAdd ----------------
__global__ __launch_bounds__(256) void k1_M(const float* __restrict__ W1,
                                            const float* __restrict__ W2) {
    __shared__ float A[32][33];
    __shared__ float Bs[32][33];
    const int t = threadIdx.x;
    const int c2_0 = blockIdx.x * 32, c1_0 = blockIdx.y * 32, kk = blockIdx.z * 32;
    {
        int r = t >> 3, c4 = (t & 7) * 4;
        float4 a = *(const float4*)&W1[(c1_0 + r) * 768 + kk + c4];
        A[r][c4] = a.x; A[r][c4 + 1] = a.y; A[r][c4 + 2] = a.z; A[r][c4 + 3] = a.w;
        float4 b = *(const float4*)&W2[(c2_0 + r) * 768 + 256 + kk + c4];
        Bs[r][c4] = b.x; Bs[r][c4 + 1] = b.y; Bs[r][c4 + 2] = b.z; Bs[r][c4 + 3] = b.w;
    }
    __syncthreads();
    const int ty = t >> 4, tx = t & 15;
    float a00 = 0.f, a01 = 0.f, a10 = 0.f, a11 = 0.f;
    #pragma unroll
    for (int k = 0; k < 32; ++k) {
        float x0 = A[ty * 2][k], x1 = A[ty * 2 + 1][k];
        float y0 = Bs[tx * 2][k], y1 = Bs[tx * 2 + 1][k];
        a00 += x0 * y0; a01 += x0 * y1; a10 += x1 * y0; a11 += x1 * y1;
    }
    atomicAdd(&g_M[(c1_0 + ty * 2)     * 256 + c2_0 + tx * 2],     a00);
    atomicAdd(&g_M[(c1_0 + ty * 2)     * 256 + c2_0 + tx * 2 + 1], a01);
    atomicAdd(&g_M[(c1_0 + ty * 2 + 1) * 256 + c2_0 + tx * 2],     a10);
    atomicAdd(&g_M[(c1_0 + ty * 2 + 1) * 256 + c2_0 + tx * 2 + 1], a11);
}

// ---------------- Kernel 1b: split M -> interleaved {hi,lo} pairs ----------------
__global__ __launch_bounds__(256) void k1b_split() {
    const int idx = (blockIdx.x * 256 + threadIdx.x) * 4;
    float4 v = *(const float4*)&g_M[idx];
    uint32_t h0 = tf32_hi(v.x), h1 = tf32_hi(v.y), h2 = tf32_hi(v.z), h3 = tf32_hi(v.w);
    float4 o0 = make_float4(__uint_as_float(h0), __uint_as_float(tf32_lo(v.x, h0)),
                            __uint_as_float(h1), __uint_as_float(tf32_lo(v.y, h1)));
    float4 o1 = make_float4(__uint_as_float(h2), __uint_as_float(tf32_lo(v.z, h2)),
                            __uint_as_float(h3), __uint_as_float(tf32_lo(v.w, h3)));
    *(float4*)&g_Mhl[2 * idx]     = o0;
    *(float4*)&g_Mhl[2 * idx + 4] = o1;
}

// ---------------- Kernel 2: U = HSI^T x M via pre-split tf32 pairs ----------------
// Block: 512 thr, tile 128 l x 256 c2, K=256 in 8 chunks of 32.
// smem (floats): Ahl[32][264] | Araw0[32][136] | Araw1 | Bhl0[32][520] | Bhl1
#define PAH  264
#define PAR  136
#define PBH  520
#define OFF_AHL  0
#define OFF_AR0  (32 * PAH)                        // 8448
#define OFF_AR1  (OFF_AR0 + 32 * PAR)              // 12800
#define OFF_BH0  (OFF_AR1 + 32 * PAR)              // 17152
#define OFF_BH1  (OFF_BH0 + 32 * PBH)              // 33792
#define K2_F     (OFF_BH1 + 32 * PBH)              // 50432 floats
#define K2_SMEM  (K2_F * 4)                        // 201728 B
#define UPIT 132

__global__ __launch_bounds__(512, 1) void k2_U(const float* __restrict__ HSI) {
    extern __shared__ float sm[];
    const int t = threadIdx.x, wid = t >> 5, lane = t & 31;
    const int g = lane >> 2, t4 = lane & 3;
    const int b = blockIdx.y, l0 = blockIdx.x * 128;
    const float* Hb = HSI + (size_t)b * C_DIM * L_DIM;
    const uint32_t sbase = smem_u32(sm);

    const int mw = (wid >> 2) * 32;        // 4 m-warps
    const int nw = (wid & 3) * 64;         // 4 n-warps

    float d[2][8][4];
    #pragma unroll
    for (int mt = 0; mt < 2; ++mt)
        #pragma unroll
        for (int nt = 0; nt < 8; ++nt)
            #pragma unroll
            for (int i = 0; i < 4; ++i) d[mt][nt][i] = 0.f;

    // chunk 0 copies
    {
        #pragma unroll
        for (int q = 0; q < 2; ++q) {               // A raw: 1024 quads
            int idx = t + q * 512;
            int r = idx >> 5, qc = (idx & 31) * 4;
            cp16(sbase + (uint32_t)((OFF_AR0 + r * PAR + qc) * 4),
                 &Hb[(size_t)r * L_DIM + l0 + qc]);
        }
        #pragma unroll
        for (int q = 0; q < 8; ++q) {               // B pre-split: 4096 quads
            int idx = t + q * 512;
            int r = idx >> 7, qc = (idx & 127) * 4;
            cp16(sbase + (uint32_t)((OFF_BH0 + r * PBH + qc) * 4),
                 &g_Mhl[r * 512 + qc]);
        }
        cp_commit();
    }

    for (int ch = 0; ch < 8; ++ch) {
        if (ch < 7) {
            const int p = (ch + 1) & 1;
            const int kk = (ch + 1) * 32;
            const int offA = p ? OFF_AR1 : OFF_AR0;
            const int offB = p ? OFF_BH1 : OFF_BH0;
            #pragma unroll
            for (int q = 0; q < 2; ++q) {
                int idx = t + q * 512;
                int r = idx >> 5, qc = (idx & 31) * 4;
                cp16(sbase + (uint32_t)((offA + r * PAR + qc) * 4),
                     &Hb[(size_t)(kk + r) * L_DIM + l0 + qc]);
            }
            #pragma unroll
            for (int q = 0; q < 8; ++q) {
                int idx = t + q * 512;
                int r = idx >> 7, qc = (idx & 127) * 4;
                cp16(sbase + (uint32_t)((offB + r * PBH + qc) * 4),
                     &g_Mhl[(kk + r) * 512 + qc]);
            }
            cp_commit();
            cp_wait<1>();
        } else {
            cp_wait<0>();
        }
        __syncthreads();   // raw chunk ch ready; prev compute done -> Ahl reusable

        // stage-split A: Araw[ch&1] (32x128) -> Ahl interleaved pairs
        {
            const float* Ar = sm + ((ch & 1) ? OFF_AR1 : OFF_AR0);
            #pragma unroll
            for (int q = 0; q < 8; ++q) {
                int idx = t + q * 512;
                int r = idx >> 7, c = idx & 127;
                float v = Ar[r * PAR + c];
                uint32_t h = tf32_hi(v);
                float2 pr = make_float2(__uint_as_float(h),
                                        __uint_as_float(tf32_lo(v, h)));
                *(float2*)&sm[OFF_AHL + r * PAH + 2 * c] = pr;
            }
        }
        __syncthreads();

        const float* Bs = sm + ((ch & 1) ? OFF_BH1 : OFF_BH0);

        #pragma unroll
        for (int s = 0; s < 4; ++s) {
            const int r0 = 8 * s + t4, r1 = r0 + 4;
            uint32_t ah[2][4], al[2][4];
            #pragma unroll
            for (int mt = 0; mt < 2; ++mt) {
                const int m0 = mw + 16 * mt + g;
                float2 p0 = *(const float2*)&sm[OFF_AHL + r0 * PAH + 2 * m0];
                float2 p1 = *(const float2*)&sm[OFF_AHL + r0 * PAH + 2 * (m0 + 8)];
                float2 p2 = *(const float2*)&sm[OFF_AHL + r1 * PAH + 2 * m0];
                float2 p3 = *(const float2*)&sm[OFF_AHL + r1 * PAH + 2 * (m0 + 8)];
                ah[mt][0] = __float_as_uint(p0.x); al[mt][0] = __float_as_uint(p0.y);
                ah[mt][1] = __float_as_uint(p1.x); al[mt][1] = __float_as_uint(p1.y);
                ah[mt][2] = __float_as_uint(p2.x); al[mt][2] = __float_as_uint(p2.y);
                ah[mt][3] = __float_as_uint(p3.x); al[mt][3] = __float_as_uint(p3.y);
            }
            #pragma unroll
            for (int ng = 0; ng < 2; ++ng) {
                uint32_t bh[4][2], bl[4][2];
                #pragma unroll
                for (int q = 0; q < 4; ++q) {
                    const int n0 = nw + 8 * (ng * 4 + q) + g;
                    float2 p0 = *(const float2*)&Bs[r0 * PBH + 2 * n0];
                    float2 p1 = *(const float2*)&Bs[r1 * PBH + 2 * n0];
                    bh[q][0] = __float_as_uint(p0.x); bl[q][0] = __float_as_uint(p0.y);
                    bh[q][1] = __float_as_uint(p1.x); bl[q][1] = __float_as_uint(p1.y);
                }
                #pragma unroll
                for (int mt = 0; mt < 2; ++mt)
                    #pragma unroll
                    for (int q = 0; q < 4; ++q)
                        mma8(d[mt][ng * 4 + q], ah[mt], bh[q]);
                #pragma unroll
                for (int mt = 0; mt < 2; ++mt)
                    #pragma unroll
                    for (int q = 0; q < 4; ++q)
                        mma8(d[mt][ng * 4 + q], ah[mt], bl[q]);
                #pragma unroll
                for (int mt = 0; mt < 2; ++mt)
                    #pragma unroll
                    for (int q = 0; q < 4; ++q)
                        mma8(d[mt][ng * 4 + q], al[mt], bh[q]);
            }
        }
    }
    __syncthreads();

    // epilogue: stage Usm[c2(256)][l(128)] pitch 132 (128KB, buffers now free), coalesced STG
    float* Usm = sm;
    float* Ub = g_U + (size_t)b * C_DIM * L_DIM;
    #pragma unroll
    for (int mt = 0; mt < 2; ++mt) {
        int row0 = mw + 16 * mt + g;
        #pragma unroll
        for (int nt = 0; nt < 8; ++nt) {
            int col0 = nw + 8 * nt + 2 * t4;
            Usm[col0 * UPIT + row0]           = d[mt][nt][0];
            Usm[(col0 + 1) * UPIT + row0]     = d[mt][nt][1];
            Usm[col0 * UPIT + row0 + 8]       = d[mt][nt][2];
            Usm[(col0 + 1) * UPIT + row0 + 8] = d[mt][nt][3];
        }
    }
    __syncthreads();
    for (int i = t; i < 256 * 32; i += 512) {
        int c2 = i >> 5, q = (i & 31) * 4;
        float4 v = *(const float4*)&Usm[c2 * UPIT + q];
        *(float4*)&Ub[(size_t)c2 * L_DIM + l0 + q] = v;
    }
}

// ---------------- Kernel 3: scores + argmax -> offsets ----------------
__global__ __launch_bounds__(288) void k3_attn(const float* __restrict__ MSI,
                                               float* __restrict__ out) {
    __shared__ __align__(16) float us[256][33];
    __shared__ float sc[288];
    const int t = threadIdx.x;
    const int b = blockIdx.y;
    const int l0 = blockIdx.x * 32;
    const int m0 = blockIdx.x * 288;
    const float* Mb = MSI + (size_t)b * C_DIM * LM_DIM;
    const float* Ub = g_U + (size_t)b * C_DIM * L_DIM;

    for (int i = t; i < 256 * 32; i += 288) {
        int c2 = i >> 5, l = i & 31;
        us[c2][l] = Ub[(size_t)c2 * L_DIM + l0 + l];
    }
    __syncthreads();

    const int m = m0 + t;
    const int ll = t / 9;
    const float* mp = Mb + m;
    float acc = 0.f;
    #pragma unroll 8
    for (int c2 = 0; c2 < 256; ++c2)
        acc += us[c2][ll] * mp[c2 * LM_DIM];
    sc[t] = acc;
    __syncthreads();

    if (t < 32) {
        float best = sc[t * 9];
        int bn = 0;
        #pragma unroll
        for (int j = 1; j < 9; ++j) {
            float v = sc[t * 9 + j];
            if (v > best) { best = v; bn = j; }   // strict > = first max (jnp.argmax)
        }
        float2 o = make_float2((float)(bn / 3) - 1.f, (float)(bn % 3) - 1.f);
        *(float2*)&out[(size_t)(b * L_DIM + l0 + t) * 2] = o;
    }
}

// ---------------- launch ----------------
extern "C" void kernel_launch(void* const* d_in, const int* in_sizes, int n_in,
                              void* d_out, int out_size) {
    const float* HSI = (const float*)d_in[2];
    const float* MSI = (const float*)d_in[3];
    const float* W1  = (const float*)d_in[4];
    const float* W2  = (const float*)d_in[5];
    float* out = (float*)d_out;

    void* mp = nullptr;
    cudaGetSymbolAddress(&mp, g_M);
    cudaMemsetAsync(mp, 0, C_DIM * C_DIM * sizeof(float), 0);

    k1_M<<<dim3(8, 8, 8), 256>>>(W1, W2);
    k1b_split<<<64, 256>>>();

    cudaFuncSetAttribute(k2_U, cudaFuncAttributeMaxDynamicSharedMemorySize, K2_SMEM);
    k2_U<<<dim3(32, 4), 512, K2_SMEM>>>(HSI);

    k3_attn<<<dim3(128, 4), 288>>>(MSI, out);
}

// round 10
// speedup vs baseline: 2.1789x; 1.2041x over previous
#include <cuda_runtime.h>
#include <cuda_fp16.h>
#include <cstdint>

#define C_DIM  256
#define L_DIM  4096
#define LM_DIM 36864
#define B_DIM  4

__device__ float    g_M[C_DIM * C_DIM];              // M[c1][c2] fp32
__device__ uint32_t g_Bpk[128 * 256 * 2];            // [k2][n]{hi, lo*2048} f16x2
__device__ float    g_U[B_DIM * C_DIM * L_DIM];      // U[b][c2][l] (x256 scale)

// ---------------- helpers ----------------
__device__ __forceinline__ uint32_t smem_u32(const void* p) {
    uint32_t a;
    asm("{ .reg .u64 t; cvta.to.shared.u64 t, %1; cvt.u32.u64 %0, t; }" : "=r"(a) : "l"(p));
    return a;
}
__device__ __forceinline__ void cp16(uint32_t dst, const void* src) {
    asm volatile("cp.async.cg.shared.global [%0], [%1], 16;" :: "r"(dst), "l"(src) : "memory");
}
__device__ __forceinline__ void cp_commit() {
    asm volatile("cp.async.commit_group;" ::: "memory");
}
template <int N>
__device__ __forceinline__ void cp_wait() {
    asm volatile("cp.async.wait_group %0;" :: "n"(N) : "memory");
}
// split x -> f16 hi + f16 lo*2048 (lo scaled out of subnormal range)
__device__ __forceinline__ void split_hl(float x, uint32_t& h, uint32_t& l) {
    __half hh = __float2half_rn(x);
    float lo = (x - __half2float(hh)) * 2048.0f;
    h = (uint32_t)__half_as_ushort(hh);
    l = (uint32_t)__half_as_ushort(__float2half_rn(lo));
}
__device__ __forceinline__ void mma16(float* d, const uint32_t* a, const uint32_t* b) {
    asm volatile(
        "mma.sync.aligned.m16n8k16.row.col.f32.f16.f16.f32 "
        "{%0,%1,%2,%3}, {%4,%5,%6,%7}, {%8,%9}, {%0,%1,%2,%3};"
        : "+f"(d[0]), "+f"(d[1]), "+f"(d[2]), "+f"(d[3])
        : "r"(a[0]), "r"(a[1]), "r"(a[2]), "r"(a[3]), "r"(b[0]), "r"(b[1]));
}

// ---------------- Kernel 1: M[c1][c2], 8-way k-split + atomicAdd ----------------
__global__ __launch_bounds__(256) void k1_M(const float* __restrict__ W1,
                                            const float* __restrict__ W2) {
    __shared__ float A[32][33];
    __shared__ float Bs[32][33];
    const int t = threadIdx.x;
    const int c2_0 = blockIdx.x * 32, c1_0 = blockIdx.y * 32, kk = blockIdx.z * 32;
    {
        int r = t >> 3, c4 = (t & 7) * 4;
        float4 a = *(const float4*)&W1[(c1_0 + r) * 768 + kk + c4];
        A[r][c4] = a.x; A[r][c4 + 1] = a.y; A[r][c4 + 2] = a.z; A[r][c4 + 3] = a.w;
        float4 b = *(const float4*)&W2[(c2_0 + r) * 768 + 256 + kk + c4];
        Bs[r][c4] = b.x; Bs[r][c4 + 1] = b.y; Bs[r][c4 + 2] = b.z; Bs[r][c4 + 3] = b.w;
    }
    __syncthreads();
    const int ty = t >> 4, tx = t & 15;
    float a00 = 0.f, a01 = 0.f, a10 = 0.f, a11 = 0.f;
    #pragma unroll
    for (int k = 0; k < 32; ++k) {
        float x0 = A[ty * 2][k], x1 = A[ty * 2 + 1][k];
        float y0 = Bs[tx * 2][k], y1 = Bs[tx * 2 + 1][k];
        a00 += x0 * y0; a01 += x0 * y1; a10 += x1 * y0; a11 += x1 * y1;
    }
    atomicAdd(&g_M[(c1_0 + ty * 2)     * 256 + c2_0 + tx * 2],     a00);
    atomicAdd(&g_M[(c1_0 + ty * 2)     * 256 + c2_0 + tx * 2 + 1], a01);
    atomicAdd(&g_M[(c1_0 + ty * 2 + 1) * 256 + c2_0 + tx * 2],     a10);
    atomicAdd(&g_M[(c1_0 + ty * 2 + 1) * 256 + c2_0 + tx * 2 + 1], a11);
}

// ---------------- Kernel 1b: pack M*256 -> f16 {hi, lo*2048} k-pairs [k2][n] ----------------
__global__ __launch_bounds__(256) void k1b_pack() {
    const int idx = blockIdx.x * 256 + threadIdx.x;     // 32768 = 128 k2 x 256 n
    const int k2 = idx >> 8, n = idx & 255;
    float x0 = g_M[(2 * k2)     * 256 + n] * 256.0f;
    float x1 = g_M[(2 * k2 + 1) * 256 + n] * 256.0f;
    uint32_t h0, l0, h1, l1;
    split_hl(x0, h0, l0);
    split_hl(x1, h1, l1);
    uint2 v;
    v.x = h0 | (h1 << 16);      // hi pack (low half = even k)
    v.y = l0 | (l1 << 16);      // lo*2048 pack
    *(uint2*)&g_Bpk[idx * 2] = v;
}

// ---------------- Kernel 2: U = HSI^T x M, f16 split w/ scaled-lo cross accumulators ----------------
// Tile 128 l x 64 c2; K=256 in 8 chunks of 32 (16 k-pairs each).
// smem u32: APK 16x264 | AR0 32x136 (f32) | AR1 | B0 16x136 | B1
#define PAU 264
#define PAR 136
#define PBU 136
#define OFF_APK 0
#define OFF_AR0 (16 * PAU)                 // 4224
#define OFF_AR1 (OFF_AR0 + 32 * PAR)       // 8576
#define OFF_B0  (OFF_AR1 + 32 * PAR)       // 12928
#define OFF_B1  (OFF_B0 + 16 * PBU)        // 15104
#define K2_F    (OFF_B1 + 16 * PBU)        // 17280 u32
#define K2_SMEM (K2_F * 4)                 // 69120 B
#define UPIT 132

__global__ __launch_bounds__(256, 2) void k2_U(const float* __restrict__ HSI) {
    extern __shared__ uint32_t smu[];
    float* smf = (float*)smu;
    const int t = threadIdx.x, wid = t >> 5, lane = t & 31;
    const int g = lane >> 2, t4 = lane & 3;
    const int b = blockIdx.z, c2_0 = blockIdx.y * 64, l0 = blockIdx.x * 128;
    const float* Hb = HSI + (size_t)b * C_DIM * L_DIM;
    const uint32_t sbase = smem_u32(smu);
    const int mw = (wid >> 1) * 32;        // 4 m-warps (32 l each)
    const int nw = (wid & 1) * 32;         // 2 n-warps (32 c2 each)

    float dh[2][4][4], dc[2][4][4];
    #pragma unroll
    for (int mt = 0; mt < 2; ++mt)
        #pragma unroll
        for (int nt = 0; nt < 4; ++nt)
            #pragma unroll
            for (int i = 0; i < 4; ++i) { dh[mt][nt][i] = 0.f; dc[mt][nt][i] = 0.f; }

    // chunk 0 copies
    {
        #pragma unroll
        for (int q = 0; q < 4; ++q) {             // A raw: 32 rows x 32 quads (f32)
            int idx = t + q * 256;
            int r = idx >> 5, c = (idx & 31) * 4;
            cp16(sbase + (uint32_t)((OFF_AR0 + r * PAR + c) * 4),
                 &Hb[(size_t)r * L_DIM + l0 + c]);
        }
        #pragma unroll
        for (int q = 0; q < 2; ++q) {             // B pack: 16 rows x 32 quads (u32)
            int idx = t + q * 256;
            int r = idx >> 5, c = (idx & 31) * 4;
            cp16(sbase + (uint32_t)((OFF_B0 + r * PBU + c) * 4),
                 &g_Bpk[(r * 256 + c2_0) * 2 + c]);
        }
        cp_commit();
    }

    for (int ch = 0; ch < 8; ++ch) {
        if (ch < 7) {
            const int p = (ch + 1) & 1;
            const int kk = (ch + 1) * 32, k2r0 = (ch + 1) * 16;
            const int offA = p ? OFF_AR1 : OFF_AR0;
            const int offB = p ? OFF_B1 : OFF_B0;
            #pragma unroll
            for (int q = 0; q < 4; ++q) {
                int idx = t + q * 256;
                int r = idx >> 5, c = (idx & 31) * 4;
                cp16(sbase + (uint32_t)((offA + r * PAR + c) * 4),
                     &Hb[(size_t)(kk + r) * L_DIM + l0 + c]);
            }
            #pragma unroll
            for (int q = 0; q < 2; ++q) {
                int idx = t + q * 256;
                int r = idx >> 5, c = (idx & 31) * 4;
                cp16(sbase + (uint32_t)((offB + r * PBU + c) * 4),
                     &g_Bpk[((k2r0 + r) * 256 + c2_0) * 2 + c]);
            }
            cp_commit();
            cp_wait<1>();
        } else {
            cp_wait<0>();
        }
        __syncthreads();   // prev compute done (APK reusable) + chunk ch landed

        // stage-split A: raw f32 [32][128] -> APK [kpair 16][m 128] {hi, lo*2048}
        {
            const float* Ar = smf + ((ch & 1) ? OFF_AR1 : OFF_AR0);
            #pragma unroll
            for (int q = 0; q < 8; ++q) {
                int idx = t + q * 256;
                int k2r = idx >> 7, m = idx & 127;
                float x0 = Ar[(2 * k2r)     * PAR + m];
                float x1 = Ar[(2 * k2r + 1) * PAR + m];
                uint32_t h0, lo0, h1, lo1;
                split_hl(x0, h0, lo0);
                split_hl(x1, h1, lo1);
                uint2 v;
                v.x = h0 | (h1 << 16);
                v.y = lo0 | (lo1 << 16);
                *(uint2*)&smu[OFF_APK + k2r * PAU + 2 * m] = v;
            }
        }
        __syncthreads();

        const uint32_t* Bp = smu + ((ch & 1) ? OFF_B1 : OFF_B0);

        #pragma unroll
        for (int s = 0; s < 2; ++s) {
            const int kr0 = 8 * s + t4, kr1 = kr0 + 4;
            uint32_t ah[2][4], al[2][4];
            #pragma unroll
            for (int mt = 0; mt < 2; ++mt) {
                const int m0 = mw + 16 * mt + g;
                uint2 p0 = *(const uint2*)&smu[OFF_APK + kr0 * PAU + 2 * m0];
                uint2 p1 = *(const uint2*)&smu[OFF_APK + kr0 * PAU + 2 * (m0 + 8)];
                uint2 p2 = *(const uint2*)&smu[OFF_APK + kr1 * PAU + 2 * m0];
                uint2 p3 = *(const uint2*)&smu[OFF_APK + kr1 * PAU + 2 * (m0 + 8)];
                ah[mt][0] = p0.x; al[mt][0] = p0.y;
                ah[mt][1] = p1.x; al[mt][1] = p1.y;
                ah[mt][2] = p2.x; al[mt][2] = p2.y;
                ah[mt][3] = p3.x; al[mt][3] = p3.y;
            }
            uint32_t bh[4][2], bl[4][2];
            #pragma unroll
            for (int q = 0; q < 4; ++q) {
                const int n0 = nw + 8 * q + g;
                uint2 p0 = *(const uint2*)&Bp[kr0 * PBU + 2 * n0];
                uint2 p1 = *(const uint2*)&Bp[kr1 * PBU + 2 * n0];
                bh[q][0] = p0.x; bl[q][0] = p0.y;
                bh[q][1] = p1.x; bl[q][1] = p1.y;
            }
            // hi*hi -> dh ; hi*lo' + lo'*hi -> dc (scaled 2048x)
            #pragma unroll
            for (int mt = 0; mt < 2; ++mt)
                #pragma unroll
                for (int q = 0; q < 4; ++q)
                    mma16(dh[mt][q], ah[mt], bh[q]);
            #pragma unroll
            for (int mt = 0; mt < 2; ++mt)
                #pragma unroll
                for (int q = 0; q < 4; ++q)
                    mma16(dc[mt][q], ah[mt], bl[q]);
            #pragma unroll
            for (int mt = 0; mt < 2; ++mt)
                #pragma unroll
                for (int q = 0; q < 4; ++q)
                    mma16(dc[mt][q], al[mt], bh[q]);
        }
    }
    __syncthreads();

    // combine + epilogue: Usm[c2 64][l 128] pitch 132, coalesced stores
    float* Usm = smf;
    float* Ub = g_U + (size_t)b * C_DIM * L_DIM;
    const float inv = 4.8828125e-4f;   // 1/2048
    #pragma unroll
    for (int mt = 0; mt < 2; ++mt) {
        int row0 = mw + 16 * mt + g;
        #pragma unroll
        for (int nt = 0; nt < 4; ++nt) {
            int col0 = nw + 8 * nt + 2 * t4;
            Usm[col0 * UPIT + row0]           = fmaf(dc[mt][nt][0], inv, dh[mt][nt][0]);
            Usm[(col0 + 1) * UPIT + row0]     = fmaf(dc[mt][nt][1], inv, dh[mt][nt][1]);
            Usm[col0 * UPIT + row0 + 8]       = fmaf(dc[mt][nt][2], inv, dh[mt][nt][2]);
            Usm[(col0 + 1) * UPIT + row0 + 8] = fmaf(dc[mt][nt][3], inv, dh[mt][nt][3]);
        }
    }
    __syncthreads();
    for (int i = t; i < 64 * 32; i += 256) {
        int c2 = i >> 5, q = (i & 31) * 4;
        float4 v = *(const float4*)&Usm[c2 * UPIT + q];
        *(float4*)&Ub[(size_t)(c2_0 + c2) * L_DIM + l0 + q] = v;
    }
}

// ---------------- Kernel 3: scores + argmax, float2/thread, 64-l blocks ----------------
#define K3_SMEM (256 * 68 * 4)   // us[256][68]

__global__ __launch_bounds__(288) void k3_attn(const float* __restrict__ MSI,
                                               float* __restrict__ out) {
    extern __shared__ float us[];          // [c2][l] pitch 68
    __shared__ float sc[576];
    const int t = threadIdx.x;
    const int b = blockIdx.y;
    const int l0 = blockIdx.x * 64;
    const float* Ub = g_U + (size_t)b * C_DIM * L_DIM;

    for (int i = t; i < 256 * 64; i += 288) {
        int c2 = i >> 6, l = i & 63;
        us[c2 * 68 + l] = Ub[(size_t)c2 * L_DIM + l0 + l];
    }
    __syncthreads();

    const int ll0 = (2 * t) / 9, ll1 = (2 * t + 1) / 9;
    const float* mp = MSI + (size_t)b * C_DIM * LM_DIM + (size_t)l0 * 9 + 2 * t;
    float acc0 = 0.f, acc1 = 0.f;
    #pragma unroll 8
    for (int c2 = 0; c2 < 256; ++c2) {
        float2 v = *(const float2*)&mp[(size_t)c2 * LM_DIM];
        acc0 += us[c2 * 68 + ll0] * v.x;
        acc1 += us[c2 * 68 + ll1] * v.y;
    }
    sc[2 * t] = acc0;
    sc[2 * t + 1] = acc1;
    __syncthreads();

    if (t < 64) {
        float best = sc[t * 9];
        int bn = 0;
        #pragma unroll
        for (int j = 1; j < 9; ++j) {
            float v = sc[t * 9 + j];
            if (v > best) { best = v; bn = j; }   // strict > = first max (jnp.argmax)
        }
        float2 o = make_float2((float)(bn / 3) - 1.f, (float)(bn % 3) - 1.f);
        *(float2*)&out[(size_t)(b * L_DIM + l0 + t) * 2] = o;
    }
}

// ---------------- launch ----------------
extern "C" void kernel_launch(void* const* d_in, const int* in_sizes, int n_in,
                              void* d_out, int out_size) {
    const float* HSI = (const float*)d_in[2];
    const float* MSI = (const float*)d_in[3];
    const float* W1  = (const float*)d_in[4];
    const float* W2  = (const float*)d_in[5];
    float* out = (float*)d_out;

    void* mp = nullptr;
    cudaGetSymbolAddress(&mp, g_M);
    cudaMemsetAsync(mp, 0, C_DIM * C_DIM * sizeof(float), 0);

    k1_M<<<dim3(8, 8, 8), 256>>>(W1, W2);
    k1b_pack<<<128, 256>>>();

    cudaFuncSetAttribute(k2_U, cudaFuncAttributeMaxDynamicSharedMemorySize, K2_SMEM);
    k2_U<<<dim3(32, 4, 4), 256, K2_SMEM>>>(HSI);

    cudaFuncSetAttribute(k3_attn, cudaFuncAttributeMaxDynamicSharedMemorySize, K3_SMEM);
    k3_attn<<<dim3(64, 4), 288, K3_SMEM>>>(MSI, out);
}